// round 6
// baseline (speedup 1.0000x reference)
#include <cuda_runtime.h>
#include <cstdint>

#define T_LEN   4096
#define D_MODEL 1024
#define NHEAD   8
#define HDIM    128
#define ATTN_SCALE 0.12f

// ---------------- tf32 mma helpers ------------------------------------------
__device__ __forceinline__ unsigned f2tf(float f) {
    unsigned u; asm("cvt.rna.tf32.f32 %0, %1;" : "=r"(u) : "f"(f)); return u;
}
__device__ __forceinline__ void mma_tf32(float* d,
    unsigned a0, unsigned a1, unsigned a2, unsigned a3,
    unsigned b0, unsigned b1) {
    asm volatile("mma.sync.aligned.m16n8k8.row.col.f32.tf32.tf32.f32 "
        "{%0,%1,%2,%3},{%4,%5,%6,%7},{%8,%9},{%0,%1,%2,%3};"
        : "+f"(d[0]), "+f"(d[1]), "+f"(d[2]), "+f"(d[3])
        : "r"(a0), "r"(a1), "r"(a2), "r"(a3), "r"(b0), "r"(b1));
}
__device__ __forceinline__ int icol8(int k) {
    return (k & ~7) | ((k & 3) << 1) | ((k >> 2) & 1);
}
__device__ __forceinline__ float fexp(float x) {
    float t = x * 1.4426950408889634f;
    float f = floorf(t);
    float r = t - f;
    float p = 1.3400000e-3f;
    p = fmaf(p, r, 9.6770508e-3f);
    p = fmaf(p, r, 5.5503310e-2f);
    p = fmaf(p, r, 2.4022652e-1f);
    p = fmaf(p, r, 6.9314718e-1f);
    p = fmaf(p, r, 1.0f);
    int e = (int)f;
    e = max(e, -127);
    float s = __int_as_float((unsigned)(e + 127) << 23);
    return p * s;
}
__device__ __forceinline__ void cp16(void* smem_ptr, const void* gptr) {
    unsigned sa = (unsigned)__cvta_generic_to_shared(smem_ptr);
    asm volatile("cp.async.cg.shared.global [%0], [%1], 16;" :: "r"(sa), "l"(gptr));
}
#define CP_COMMIT() asm volatile("cp.async.commit_group;")
#define CP_WAIT(N)  asm volatile("cp.async.wait_group %0;" :: "n"(N))
#define CP_WAIT_ALL() asm volatile("cp.async.wait_all;")

// ---------------- scratch ----------------------------------------------------
__device__ float g_qkv[(size_t)T_LEN * 3 * D_MODEL];
__device__ float g_q[(size_t)NHEAD * T_LEN * HDIM];   // tf32, icol8, *scale
__device__ float g_k[(size_t)NHEAD * T_LEN * HDIM];   // tf32, icol8
__device__ float g_v[(size_t)NHEAD * T_LEN * HDIM];   // tf32, natural
__device__ float g_y[(size_t)T_LEN * D_MODEL];        // tf32, icol8
__device__ float g_xi[(size_t)T_LEN * D_MODEL];       // preconv x (icol8)
__device__ float g_wi[(size_t)3 * D_MODEL * D_MODEL]; // preconv qkv_w (icol8)
__device__ float g_cpi[(size_t)D_MODEL * D_MODEL];    // preconv c_proj_w (icol8)

// ---------------- pre-pass: tf32 round + icol8 interleave (K=1024) -----------
__global__ __launch_bounds__(256) void conv_ilv(const float* __restrict__ in,
                                                float* __restrict__ out, int n4) {
    int i = blockIdx.x * 256 + threadIdx.x;
    if (i >= n4) return;
    float4 v = ((const float4*)in)[i];
    int idx = i * 4;
    int row = idx >> 10;
    int c = idx & 1023;
    int base = row * 1024 + (c & ~7);
    int h = (c >> 2) & 1;
    out[base + h + 0] = __uint_as_float(f2tf(v.x));
    out[base + h + 2] = __uint_as_float(f2tf(v.y));
    out[base + h + 4] = __uint_as_float(f2tf(v.z));
    out[base + h + 6] = __uint_as_float(f2tf(v.w));
}

// ---------------- tf32 NT GEMM v3: preconverted inputs, cp.async 3-stage -----
// C[M,N] = A[M,K] B[N,K]^T. 256 thr, 8 warps (4Mx2N), warp 32x64, BK=16.
#define GST 20
#define GSTAGE (128 * GST)
__global__ __launch_bounds__(256, 2) void gemm3(const float* __restrict__ A,
                                                const float* __restrict__ B,
                                                float* __restrict__ C,
                                                int M, int N, int K) {
    extern __shared__ unsigned smu[];
    const int bm = blockIdx.y * 128, bn = blockIdx.x * 128;
    const int tid = threadIdx.x;
    const int wid = tid >> 5, lane = tid & 31;
    const int wm = (wid >> 1) * 32, wn = (wid & 1) * 64;
    const int lq = lane >> 2, lr = lane & 3;

    const int row0 = tid >> 2;
    const int ch0  = (tid & 3) * 4;

    float acc[2][8][4];
#pragma unroll
    for (int mf = 0; mf < 2; mf++)
#pragma unroll
        for (int nf = 0; nf < 8; nf++)
#pragma unroll
            for (int j = 0; j < 4; j++) acc[mf][nf][j] = 0.f;

    const int nk = K >> 4;

    auto issue = [&](int it, int buf) {
        unsigned* sA = smu + buf * (2 * GSTAGE);
        unsigned* sB = sA + GSTAGE;
        int k0 = it << 4;
#pragma unroll
        for (int p = 0; p < 2; p++) {
            int r = row0 + p * 64;
            cp16(&sA[r * GST + ch0], A + (size_t)(bm + r) * K + k0 + ch0);
            cp16(&sB[r * GST + ch0], B + (size_t)(bn + r) * K + k0 + ch0);
        }
    };

    issue(0, 0); CP_COMMIT();
    issue(1, 1); CP_COMMIT();

    for (int it = 0; it < nk; it++) {
        CP_WAIT(1);
        __syncthreads();
        if (it + 2 < nk) issue(it + 2, (it + 2) % 3);
        CP_COMMIT();

        const unsigned* sA = smu + (it % 3) * (2 * GSTAGE);
        const unsigned* sB = sA + GSTAGE;
#pragma unroll
        for (int ks = 0; ks < 2; ks++) {
            unsigned a[2][4];
#pragma unroll
            for (int mf = 0; mf < 2; mf++) {
                uint2 a02 = *(const uint2*)&sA[(wm + mf * 16 + lq) * GST + ks * 8 + lr * 2];
                uint2 a13 = *(const uint2*)&sA[(wm + mf * 16 + 8 + lq) * GST + ks * 8 + lr * 2];
                a[mf][0] = a02.x; a[mf][1] = a13.x; a[mf][2] = a02.y; a[mf][3] = a13.y;
            }
#pragma unroll
            for (int nf = 0; nf < 8; nf++) {
                uint2 b = *(const uint2*)&sB[(wn + nf * 8 + lq) * GST + ks * 8 + lr * 2];
                mma_tf32(acc[0][nf], a[0][0], a[0][1], a[0][2], a[0][3], b.x, b.y);
                mma_tf32(acc[1][nf], a[1][0], a[1][1], a[1][2], a[1][3], b.x, b.y);
            }
        }
    }
#pragma unroll
    for (int mf = 0; mf < 2; mf++)
#pragma unroll
        for (int nf = 0; nf < 8; nf++) {
            float* c0 = C + (size_t)(bm + wm + mf * 16 + lq) * N + bn + wn + nf * 8 + lr * 2;
            c0[0] = acc[mf][nf][0]; c0[1] = acc[mf][nf][1];
            float* c1 = c0 + 8 * (size_t)N;
            c1[0] = acc[mf][nf][2]; c1[1] = acc[mf][nf][3];
        }
}

// ---------------- RMSNorm + rotary + V blend ---------------------------------
__global__ __launch_bounds__(128) void qkv_post(const float* __restrict__ qkv,
                                                const float* __restrict__ ve,
                                                const float* __restrict__ lambdas,
                                                float* __restrict__ Q,
                                                float* __restrict__ K,
                                                float* __restrict__ V) {
    const int t = blockIdx.x, h = blockIdx.y, d = threadIdx.x;
    const int lane = d & 31, wid = d >> 5;
    const float* base = qkv + (size_t)t * (3 * D_MODEL) + h * HDIM;

    float qv = base[d];
    float kv = base[D_MODEL + d];
    float vv = base[2 * D_MODEL + d];

    float s1 = qv * qv, s2 = kv * kv;
#pragma unroll
    for (int o = 16; o; o >>= 1) {
        s1 += __shfl_xor_sync(0xffffffffu, s1, o);
        s2 += __shfl_xor_sync(0xffffffffu, s2, o);
    }
    __shared__ float w1[4], w2[4];
    if (lane == 0) { w1[wid] = s1; w2[wid] = s2; }
    __syncthreads();
    float sq = w1[0] + w1[1] + w1[2] + w1[3];
    float sk = w2[0] + w2[1] + w2[2] + w2[3];
    const float eps = 1.1920929e-7f;
    float rq = rsqrtf(sq * (1.0f / 128.0f) + eps);
    float rk = rsqrtf(sk * (1.0f / 128.0f) + eps);

    __shared__ float qs[128], ks[128];
    qs[d] = qv * rq; ks[d] = kv * rk;
    __syncthreads();

    int j = d & 63;
    float ang = (j < 32) ? exp2f((float)j * (-10.0f / 31.0f)) : 0.0f;
    float theta = (float)t * ang;
    float c, s;
    sincosf(theta, &s, &c);

    float qo, ko;
    if (d < 64) {
        qo =  qs[d] * c + qs[d + 64] * s;
        ko =  ks[d] * c + ks[d + 64] * s;
    } else {
        qo = -qs[d - 64] * s + qs[d] * c;
        ko = -ks[d - 64] * s + ks[d] * c;
    }

    float l0 = lambdas[0], l1 = lambdas[1];
    float vo = l0 * vv + l1 * ve[(size_t)t * D_MODEL + h * HDIM + d];

    size_t rb = ((size_t)h * T_LEN + t) * HDIM;
    int di = icol8(d);
    Q[rb + di] = __uint_as_float(f2tf(qo * ATTN_SCALE));
    K[rb + di] = __uint_as_float(f2tf(ko));
    V[rb + d]  = __uint_as_float(f2tf(vo));
}

// ---------------- tf32 mma causal flash attention (2 CTAs/SM) ----------------
// 256 thr, 8 warps. CTA = 128 q rows; 64-key tiles, single-buffered K/V,
// K prefetch after S-phase, V prefetch after PV. Q frags streamed from L1.
#define KVS 132
#define PSS 72
#define SM_PS  (2 * 64 * KVS)
#define SM_RS  (SM_PS + 128 * PSS)
#define SM_TOT (SM_RS + 256)
__global__ __launch_bounds__(256, 2) void attn_tf32(const float* __restrict__ Q,
                                                    const float* __restrict__ K,
                                                    const float* __restrict__ V,
                                                    float* __restrict__ Y) {
    extern __shared__ unsigned sm[];
    unsigned* Kb = sm;
    unsigned* Vb = sm + 64 * KVS;
    unsigned* Ps = sm + SM_PS;
    float* Rs = (float*)(sm + SM_RS);
    float* Li = Rs + 128;

    const int h  = blockIdx.y;
    const int qb = ((int)gridDim.x - 1 - (int)blockIdx.x) * 128;
    const int tid = threadIdx.x, wid = tid >> 5, lane = tid & 31;
    const int lq = lane >> 2, lr = lane & 3;
    const int qw = wid * 16;
    const int dw = wid * 16;

    const float* Kh = K + (size_t)h * T_LEN * HDIM;
    const float* Vh = V + (size_t)h * T_LEN * HDIM;
    const unsigned* Qr0 = (const unsigned*)(Q + (size_t)h * T_LEN * HDIM
                                            + (size_t)(qb + qw + lq) * HDIM);
    const unsigned* Qr1 = Qr0 + 8 * HDIM;

    const int ic0 = icol8(2 * lr);
    const int ic1 = icol8(2 * lr + 1);

    float ofr[16][4];
#pragma unroll
    for (int nf = 0; nf < 16; nf++)
#pragma unroll
        for (int j = 0; j < 4; j++) ofr[nf][j] = 0.f;
    float m0 = -1e30f, m1 = -1e30f, l0 = 0.f, l1 = 0.f;

    const int ntiles = qb / 64 + 2;

    auto issue_k = [&](int s0) {
#pragma unroll
        for (int p = 0; p < 8; p++) {
            int e = tid + 256 * p;
            int r = e >> 5, c = (e & 31) * 4;
            cp16(&Kb[r * KVS + c], Kh + (size_t)(s0 + r) * HDIM + c);
        }
    };
    auto issue_v = [&](int s0) {
#pragma unroll
        for (int p = 0; p < 8; p++) {
            int e = tid + 256 * p;
            int r = e >> 5, c = (e & 31) * 4;
            cp16(&Vb[r * KVS + c], Vh + (size_t)(s0 + r) * HDIM + c);
        }
    };

    issue_k(0); CP_COMMIT();
    issue_v(0); CP_COMMIT();

    for (int it = 0; it < ntiles; it++) {
        const int s0 = it * 64;
        CP_WAIT_ALL();
        __syncthreads();                       // K,V visible

        // ---- S = Q K^T ----
        float sfr[8][4];
#pragma unroll
        for (int nf = 0; nf < 8; nf++)
#pragma unroll
            for (int j = 0; j < 4; j++) sfr[nf][j] = 0.f;
#pragma unroll
        for (int ks = 0; ks < 16; ks++) {
            uint2 a02 = *(const uint2*)&Qr0[ks * 8 + lr * 2];
            uint2 a13 = *(const uint2*)&Qr1[ks * 8 + lr * 2];
#pragma unroll
            for (int nf = 0; nf < 8; nf++) {
                uint2 b = *(const uint2*)&Kb[(nf * 8 + lq) * KVS + ks * 8 + lr * 2];
                mma_tf32(sfr[nf], a02.x, a13.x, a02.y, a13.y, b.x, b.y);
            }
        }
        __syncthreads();                       // all K reads done
        if (it + 1 < ntiles) { issue_k(s0 + 64); }
        CP_COMMIT();

        // ---- masked online softmax ----
        const int q0 = qb + qw + lq, q1 = q0 + 8;
        const bool needmask = (s0 + 63) > (qb + qw);
        float r0 = -1e30f, r1 = -1e30f;
        if (needmask) {
#pragma unroll
            for (int nf = 0; nf < 8; nf++) {
                int sA = s0 + nf * 8 + 2 * lr, sB = sA + 1;
                if (sA > q0) sfr[nf][0] = -1e30f;
                if (sB > q0) sfr[nf][1] = -1e30f;
                if (sA > q1) sfr[nf][2] = -1e30f;
                if (sB > q1) sfr[nf][3] = -1e30f;
            }
        }
#pragma unroll
        for (int nf = 0; nf < 8; nf++) {
            r0 = fmaxf(r0, fmaxf(sfr[nf][0], sfr[nf][1]));
            r1 = fmaxf(r1, fmaxf(sfr[nf][2], sfr[nf][3]));
        }
        r0 = fmaxf(r0, __shfl_xor_sync(0xffffffffu, r0, 1));
        r0 = fmaxf(r0, __shfl_xor_sync(0xffffffffu, r0, 2));
        r1 = fmaxf(r1, __shfl_xor_sync(0xffffffffu, r1, 1));
        r1 = fmaxf(r1, __shfl_xor_sync(0xffffffffu, r1, 2));
        float mn0 = fmaxf(m0, r0), mn1 = fmaxf(m1, r1);
        float rs0 = fexp(m0 - mn0), rs1 = fexp(m1 - mn1);
        float sum0 = 0.f, sum1 = 0.f;
#pragma unroll
        for (int nf = 0; nf < 8; nf++) {
            float p00 = fexp(sfr[nf][0] - mn0);
            float p01 = fexp(sfr[nf][1] - mn0);
            float p10 = fexp(sfr[nf][2] - mn1);
            float p11 = fexp(sfr[nf][3] - mn1);
            sum0 += p00 + p01; sum1 += p10 + p11;
            Ps[(qw + lq) * PSS + nf * 8 + ic0]     = f2tf(p00);
            Ps[(qw + lq) * PSS + nf * 8 + ic1]     = f2tf(p01);
            Ps[(qw + 8 + lq) * PSS + nf * 8 + ic0] = f2tf(p10);
            Ps[(qw + 8 + lq) * PSS + nf * 8 + ic1] = f2tf(p11);
        }
        sum0 += __shfl_xor_sync(0xffffffffu, sum0, 1);
        sum0 += __shfl_xor_sync(0xffffffffu, sum0, 2);
        sum1 += __shfl_xor_sync(0xffffffffu, sum1, 1);
        sum1 += __shfl_xor_sync(0xffffffffu, sum1, 2);
        l0 = l0 * rs0 + sum0; m0 = mn0;
        l1 = l1 * rs1 + sum1; m1 = mn1;
        if (lr == 0) { Rs[qw + lq] = rs0; Rs[qw + 8 + lq] = rs1; }
        __syncthreads();                       // Ps/Rs ready

        // ---- rescale O^T ----
#pragma unroll
        for (int nf = 0; nf < 16; nf++) {
            float2 rr = *(const float2*)&Rs[nf * 8 + lr * 2];
            ofr[nf][0] *= rr.x; ofr[nf][1] *= rr.y;
            ofr[nf][2] *= rr.x; ofr[nf][3] *= rr.y;
        }

        // ---- O^T += V^T P^T ----
#pragma unroll
        for (int ks = 0; ks < 8; ks++) {
            unsigned a0 = Vb[(ks * 8 + lr) * KVS + dw + lq];
            unsigned a1 = Vb[(ks * 8 + lr) * KVS + dw + lq + 8];
            unsigned a2 = Vb[(ks * 8 + lr + 4) * KVS + dw + lq];
            unsigned a3 = Vb[(ks * 8 + lr + 4) * KVS + dw + lq + 8];
#pragma unroll
            for (int nf = 0; nf < 16; nf++) {
                uint2 b = *(const uint2*)&Ps[(nf * 8 + lq) * PSS + ks * 8 + lr * 2];
                mma_tf32(ofr[nf], a0, a1, a2, a3, b.x, b.y);
            }
        }
        __syncthreads();                       // all V/Ps reads done
        if (it + 1 < ntiles) { issue_v(s0 + 64); }
        CP_COMMIT();
    }

    // ---- epilogue: normalize, tf32-round, icol8-interleave into Y -----------
    if (lr == 0) { Li[qw + lq] = 1.f / l0; Li[qw + 8 + lq] = 1.f / l1; }
    __syncthreads();
    const int lqp = ((lq & 3) << 1) | (lq >> 2);   // icol8 within 8-group
    const int colbase = h * HDIM + dw;
#pragma unroll
    for (int nf = 0; nf < 16; nf++) {
        float2 li = *(const float2*)&Li[nf * 8 + lr * 2];
        int q = qb + nf * 8 + lr * 2;
        float* ya = Y + (size_t)q * D_MODEL;
        float* yb = ya + D_MODEL;
        ya[colbase + lqp]     = __uint_as_float(f2tf(ofr[nf][0] * li.x));
        yb[colbase + lqp]     = __uint_as_float(f2tf(ofr[nf][1] * li.y));
        ya[colbase + 8 + lqp] = __uint_as_float(f2tf(ofr[nf][2] * li.x));
        yb[colbase + 8 + lqp] = __uint_as_float(f2tf(ofr[nf][3] * li.y));
    }
}

// ---------------- launch ------------------------------------------------------
extern "C" void kernel_launch(void* const* d_in, const int* in_sizes, int n_in,
                              void* d_out, int out_size) {
    const float* x        = (const float*)d_in[0];
    const float* ve       = (const float*)d_in[1];
    const float* qkv_w    = (const float*)d_in[2];
    const float* lambdas  = (const float*)d_in[3];
    const float* c_proj_w = (const float*)d_in[4];
    float* out = (float*)d_out;

    float *p_qkv, *p_q, *p_k, *p_v, *p_y, *p_xi, *p_wi, *p_cpi;
    cudaGetSymbolAddress((void**)&p_qkv, g_qkv);
    cudaGetSymbolAddress((void**)&p_q, g_q);
    cudaGetSymbolAddress((void**)&p_k, g_k);
    cudaGetSymbolAddress((void**)&p_v, g_v);
    cudaGetSymbolAddress((void**)&p_y, g_y);
    cudaGetSymbolAddress((void**)&p_xi, g_xi);
    cudaGetSymbolAddress((void**)&p_wi, g_wi);
    cudaGetSymbolAddress((void**)&p_cpi, g_cpi);

    const int gemm_smem = 3 * 2 * GSTAGE * 4;       // 61440 B
    const int attn_smem = SM_TOT * 4;               // ~103 KB
    static bool attr_set = false;
    if (!attr_set) {
        cudaFuncSetAttribute(gemm3, cudaFuncAttributeMaxDynamicSharedMemorySize,
                             gemm_smem);
        cudaFuncSetAttribute(attn_tf32, cudaFuncAttributeMaxDynamicSharedMemorySize,
                             attn_smem);
        attr_set = true;
    }

    // pre-pass conversions
    conv_ilv<<<4096, 256>>>(x, p_xi, T_LEN * D_MODEL / 4);
    conv_ilv<<<3072, 256>>>(qkv_w, p_wi, 3 * D_MODEL * D_MODEL / 4);
    conv_ilv<<<1024, 256>>>(c_proj_w, p_cpi, D_MODEL * D_MODEL / 4);

    gemm3<<<dim3(3 * D_MODEL / 128, T_LEN / 128), 256, gemm_smem>>>(
        p_xi, p_wi, p_qkv, T_LEN, 3 * D_MODEL, D_MODEL);

    qkv_post<<<dim3(T_LEN, NHEAD), 128>>>(p_qkv, ve, lambdas, p_q, p_k, p_v);

    attn_tf32<<<dim3(T_LEN / 128, NHEAD), 256, attn_smem>>>(p_q, p_k, p_v, p_y);

    gemm3<<<dim3(D_MODEL / 128, T_LEN / 128), 256, gemm_smem>>>(
        p_y, p_cpi, out, T_LEN, D_MODEL, D_MODEL);
}

// round 7
// speedup vs baseline: 1.3333x; 1.3333x over previous
#include <cuda_runtime.h>
#include <cstdint>

#define T_LEN   4096
#define D_MODEL 1024
#define NHEAD   8
#define HDIM    128
#define ATTN_SCALE 0.12f

// ---------------- tf32 mma helpers ------------------------------------------
__device__ __forceinline__ unsigned f2tf(float f) {
    unsigned u; asm("cvt.rna.tf32.f32 %0, %1;" : "=r"(u) : "f"(f)); return u;
}
__device__ __forceinline__ void mma_tf32(float* d,
    unsigned a0, unsigned a1, unsigned a2, unsigned a3,
    unsigned b0, unsigned b1) {
    asm volatile("mma.sync.aligned.m16n8k8.row.col.f32.tf32.tf32.f32 "
        "{%0,%1,%2,%3},{%4,%5,%6,%7},{%8,%9},{%0,%1,%2,%3};"
        : "+f"(d[0]), "+f"(d[1]), "+f"(d[2]), "+f"(d[3])
        : "r"(a0), "r"(a1), "r"(a2), "r"(a3), "r"(b0), "r"(b1));
}
__device__ __forceinline__ int icol8(int k) {
    return (k & ~7) | ((k & 3) << 1) | ((k >> 2) & 1);
}
__device__ __forceinline__ float fexp(float x) {
    float t = x * 1.4426950408889634f;
    float f = floorf(t);
    float r = t - f;
    float p = 1.3400000e-3f;
    p = fmaf(p, r, 9.6770508e-3f);
    p = fmaf(p, r, 5.5503310e-2f);
    p = fmaf(p, r, 2.4022652e-1f);
    p = fmaf(p, r, 6.9314718e-1f);
    p = fmaf(p, r, 1.0f);
    int e = (int)f;
    e = max(e, -127);
    float s = __int_as_float((unsigned)(e + 127) << 23);
    return p * s;
}
__device__ __forceinline__ void cp16(void* smem_ptr, const void* gptr) {
    unsigned sa = (unsigned)__cvta_generic_to_shared(smem_ptr);
    asm volatile("cp.async.cg.shared.global [%0], [%1], 16;" :: "r"(sa), "l"(gptr));
}
#define CP_COMMIT() asm volatile("cp.async.commit_group;")
#define CP_WAIT(N)  asm volatile("cp.async.wait_group %0;" :: "n"(N))

// ---------------- scratch ----------------------------------------------------
__device__ float g_qkv[(size_t)T_LEN * 3 * D_MODEL];
__device__ float g_q[(size_t)NHEAD * T_LEN * HDIM];   // tf32, icol8, *scale
__device__ float g_k[(size_t)NHEAD * T_LEN * HDIM];   // tf32, icol8
__device__ float g_v[(size_t)NHEAD * T_LEN * HDIM];   // tf32, natural
__device__ float g_y[(size_t)T_LEN * D_MODEL];        // tf32, icol8
__device__ float g_xi[(size_t)T_LEN * D_MODEL];
__device__ float g_wi[(size_t)3 * D_MODEL * D_MODEL];
__device__ float g_cpi[(size_t)D_MODEL * D_MODEL];

// ---------------- pre-pass: tf32 round + icol8 interleave (K=1024) -----------
__global__ __launch_bounds__(256) void conv_ilv(const float* __restrict__ in,
                                                float* __restrict__ out, int n4) {
    int i = blockIdx.x * 256 + threadIdx.x;
    if (i >= n4) return;
    float4 v = ((const float4*)in)[i];
    int idx = i * 4;
    int row = idx >> 10;
    int c = idx & 1023;
    int base = row * 1024 + (c & ~7);
    int h = (c >> 2) & 1;
    out[base + h + 0] = __uint_as_float(f2tf(v.x));
    out[base + h + 2] = __uint_as_float(f2tf(v.y));
    out[base + h + 4] = __uint_as_float(f2tf(v.z));
    out[base + h + 6] = __uint_as_float(f2tf(v.w));
}

// ---------------- tf32 NT GEMM: cp.async 4-stage ring -------------------------
#define GST 20
#define GSTAGE (128 * GST)
#define GEMM_SMEM (4 * 2 * GSTAGE * 4)
__global__ __launch_bounds__(256, 2) void gemm3(const float* __restrict__ A,
                                                const float* __restrict__ B,
                                                float* __restrict__ C,
                                                int M, int N, int K) {
    extern __shared__ unsigned smu[];
    const int bm = blockIdx.y * 128, bn = blockIdx.x * 128;
    const int tid = threadIdx.x;
    const int wid = tid >> 5, lane = tid & 31;
    const int wm = (wid >> 1) * 32, wn = (wid & 1) * 64;
    const int lq = lane >> 2, lr = lane & 3;

    const int row0 = tid >> 2;
    const int ch0  = (tid & 3) * 4;

    float acc[2][8][4];
#pragma unroll
    for (int mf = 0; mf < 2; mf++)
#pragma unroll
        for (int nf = 0; nf < 8; nf++)
#pragma unroll
            for (int j = 0; j < 4; j++) acc[mf][nf][j] = 0.f;

    const int nk = K >> 4;

    auto issue = [&](int it, int buf) {
        unsigned* sA = smu + buf * (2 * GSTAGE);
        unsigned* sB = sA + GSTAGE;
        int k0 = it << 4;
#pragma unroll
        for (int p = 0; p < 2; p++) {
            int r = row0 + p * 64;
            cp16(&sA[r * GST + ch0], A + (size_t)(bm + r) * K + k0 + ch0);
            cp16(&sB[r * GST + ch0], B + (size_t)(bn + r) * K + k0 + ch0);
        }
    };

    issue(0, 0); CP_COMMIT();
    issue(1, 1); CP_COMMIT();
    issue(2, 2); CP_COMMIT();

    for (int it = 0; it < nk; it++) {
        CP_WAIT(2);
        __syncthreads();
        if (it + 3 < nk) issue(it + 3, (it + 3) & 3);
        CP_COMMIT();

        const unsigned* sA = smu + (it & 3) * (2 * GSTAGE);
        const unsigned* sB = sA + GSTAGE;
#pragma unroll
        for (int ks = 0; ks < 2; ks++) {
            unsigned a[2][4];
#pragma unroll
            for (int mf = 0; mf < 2; mf++) {
                uint2 a02 = *(const uint2*)&sA[(wm + mf * 16 + lq) * GST + ks * 8 + lr * 2];
                uint2 a13 = *(const uint2*)&sA[(wm + mf * 16 + 8 + lq) * GST + ks * 8 + lr * 2];
                a[mf][0] = a02.x; a[mf][1] = a13.x; a[mf][2] = a02.y; a[mf][3] = a13.y;
            }
#pragma unroll
            for (int nf = 0; nf < 8; nf++) {
                uint2 b = *(const uint2*)&sB[(wn + nf * 8 + lq) * GST + ks * 8 + lr * 2];
                mma_tf32(acc[0][nf], a[0][0], a[0][1], a[0][2], a[0][3], b.x, b.y);
                mma_tf32(acc[1][nf], a[1][0], a[1][1], a[1][2], a[1][3], b.x, b.y);
            }
        }
    }
#pragma unroll
    for (int mf = 0; mf < 2; mf++)
#pragma unroll
        for (int nf = 0; nf < 8; nf++) {
            float* c0 = C + (size_t)(bm + wm + mf * 16 + lq) * N + bn + wn + nf * 8 + lr * 2;
            c0[0] = acc[mf][nf][0]; c0[1] = acc[mf][nf][1];
            float* c1 = c0 + 8 * (size_t)N;
            c1[0] = acc[mf][nf][2]; c1[1] = acc[mf][nf][3];
        }
}

// ---------------- RMSNorm + rotary + V blend ---------------------------------
__global__ __launch_bounds__(128) void qkv_post(const float* __restrict__ qkv,
                                                const float* __restrict__ ve,
                                                const float* __restrict__ lambdas,
                                                float* __restrict__ Q,
                                                float* __restrict__ K,
                                                float* __restrict__ V) {
    const int t = blockIdx.x, h = blockIdx.y, d = threadIdx.x;
    const int lane = d & 31, wid = d >> 5;
    const float* base = qkv + (size_t)t * (3 * D_MODEL) + h * HDIM;

    float qv = base[d];
    float kv = base[D_MODEL + d];
    float vv = base[2 * D_MODEL + d];

    float s1 = qv * qv, s2 = kv * kv;
#pragma unroll
    for (int o = 16; o; o >>= 1) {
        s1 += __shfl_xor_sync(0xffffffffu, s1, o);
        s2 += __shfl_xor_sync(0xffffffffu, s2, o);
    }
    __shared__ float w1[4], w2[4];
    if (lane == 0) { w1[wid] = s1; w2[wid] = s2; }
    __syncthreads();
    float sq = w1[0] + w1[1] + w1[2] + w1[3];
    float sk = w2[0] + w2[1] + w2[2] + w2[3];
    const float eps = 1.1920929e-7f;
    float rq = rsqrtf(sq * (1.0f / 128.0f) + eps);
    float rk = rsqrtf(sk * (1.0f / 128.0f) + eps);

    __shared__ float qs[128], ks[128];
    qs[d] = qv * rq; ks[d] = kv * rk;
    __syncthreads();

    int j = d & 63;
    float ang = (j < 32) ? exp2f((float)j * (-10.0f / 31.0f)) : 0.0f;
    float theta = (float)t * ang;
    float c, s;
    sincosf(theta, &s, &c);

    float qo, ko;
    if (d < 64) {
        qo =  qs[d] * c + qs[d + 64] * s;
        ko =  ks[d] * c + ks[d + 64] * s;
    } else {
        qo = -qs[d - 64] * s + qs[d] * c;
        ko = -ks[d - 64] * s + ks[d] * c;
    }

    float l0 = lambdas[0], l1 = lambdas[1];
    float vo = l0 * vv + l1 * ve[(size_t)t * D_MODEL + h * HDIM + d];

    size_t rb = ((size_t)h * T_LEN + t) * HDIM;
    int di = icol8(d);
    Q[rb + di] = __uint_as_float(f2tf(qo * ATTN_SCALE));
    K[rb + di] = __uint_as_float(f2tf(ko));
    V[rb + d]  = __uint_as_float(f2tf(vo));
}

// ---------------- tf32 mma causal flash attention, warp-local P --------------
// 256 thr, 8 warps. CTA = 128 q rows; 64-key tiles, double-buffered K/V,
// warp-local softmax + PV (O[16q][128d] per warp, P via shfl). 1 sync/tile.
#define KVS 132
#define KVW (64 * KVS)
#define ATTN_SMEM (4 * KVW * 4)
__global__ __launch_bounds__(256) void attn_tf32(const float* __restrict__ Q,
                                                 const float* __restrict__ K,
                                                 const float* __restrict__ V,
                                                 float* __restrict__ Y) {
    extern __shared__ unsigned sm[];

    const int h  = blockIdx.y;
    const int qb = ((int)gridDim.x - 1 - (int)blockIdx.x) * 128;
    const int tid = threadIdx.x, wid = tid >> 5, lane = tid & 31;
    const int lq = lane >> 2, lr = lane & 3;
    const int qw = wid * 16;

    const uint4* Qg = (const uint4*)(Q + (size_t)h * T_LEN * HDIM);
    const float* Kh = K + (size_t)h * T_LEN * HDIM;
    const float* Vh = V + (size_t)h * T_LEN * HDIM;

    // ---- stage Q tile into smem (Kb area), extract per-warp frags -----------
#pragma unroll
    for (int p = 0; p < 16; p++) {
        int e = tid + 256 * p;
        int r = e >> 5, c = (e & 31) * 4;
        *(uint4*)&sm[r * KVS + c] = Qg[((size_t)(qb + r) * HDIM + c) >> 2];
    }
    __syncthreads();
    unsigned qa[16][4];
#pragma unroll
    for (int ks = 0; ks < 16; ks++) {
        uint2 a02 = *(const uint2*)&sm[(qw + lq) * KVS + ks * 8 + lr * 2];
        uint2 a13 = *(const uint2*)&sm[(qw + 8 + lq) * KVS + ks * 8 + lr * 2];
        qa[ks][0] = a02.x; qa[ks][1] = a13.x; qa[ks][2] = a02.y; qa[ks][3] = a13.y;
    }
    __syncthreads();

    float ofr[16][4];
#pragma unroll
    for (int nf = 0; nf < 16; nf++)
#pragma unroll
        for (int j = 0; j < 4; j++) ofr[nf][j] = 0.f;
    float m0 = -1e30f, m1 = -1e30f, l0 = 0.f, l1 = 0.f;

    const int ntiles = qb / 64 + 2;

    auto issue_kv = [&](int s0, int buf) {
        unsigned* Kb = sm + buf * KVW;
        unsigned* Vb = sm + 2 * KVW + buf * KVW;
#pragma unroll
        for (int p = 0; p < 8; p++) {
            int e = tid + 256 * p;
            int r = e >> 5, c = (e & 31) * 4;
            cp16(&Kb[r * KVS + c], Kh + (size_t)(s0 + r) * HDIM + c);
            cp16(&Vb[r * KVS + c], Vh + (size_t)(s0 + r) * HDIM + c);
        }
    };

    issue_kv(0, 0); CP_COMMIT();

    // shfl sources for P->A-fragment permutation (quad-local)
    const int srcA = (lane & ~3) | (lr >> 1);
    const int srcB = srcA + 2;
    const bool odd = (lr & 1) != 0;

    for (int it = 0; it < ntiles; it++) {
        const int s0 = it * 64;
        const int buf = it & 1;
        CP_WAIT(0);
        __syncthreads();                       // K,V (buf) visible; buf^1 free
        if (it + 1 < ntiles) issue_kv(s0 + 64, buf ^ 1);
        CP_COMMIT();

        const unsigned* Kb = sm + buf * KVW;
        const unsigned* Vb = sm + 2 * KVW + buf * KVW;

        // ---- S = Q K^T (warp rows qw..qw+15) ----
        float sfr[8][4];
#pragma unroll
        for (int nf = 0; nf < 8; nf++)
#pragma unroll
            for (int j = 0; j < 4; j++) sfr[nf][j] = 0.f;
#pragma unroll
        for (int ks = 0; ks < 16; ks++) {
#pragma unroll
            for (int nf = 0; nf < 8; nf++) {
                uint2 b = *(const uint2*)&Kb[(nf * 8 + lq) * KVS + ks * 8 + lr * 2];
                mma_tf32(sfr[nf], qa[ks][0], qa[ks][1], qa[ks][2], qa[ks][3], b.x, b.y);
            }
        }

        // ---- masked online softmax (warp-local) ----
        const int q0 = qb + qw + lq, q1 = q0 + 8;
        const bool needmask = (s0 + 63) > (qb + qw);
        float r0 = -1e30f, r1 = -1e30f;
        if (needmask) {
#pragma unroll
            for (int nf = 0; nf < 8; nf++) {
                int sA = s0 + nf * 8 + 2 * lr, sB = sA + 1;
                if (sA > q0) sfr[nf][0] = -1e30f;
                if (sB > q0) sfr[nf][1] = -1e30f;
                if (sA > q1) sfr[nf][2] = -1e30f;
                if (sB > q1) sfr[nf][3] = -1e30f;
            }
        }
#pragma unroll
        for (int nf = 0; nf < 8; nf++) {
            r0 = fmaxf(r0, fmaxf(sfr[nf][0], sfr[nf][1]));
            r1 = fmaxf(r1, fmaxf(sfr[nf][2], sfr[nf][3]));
        }
        r0 = fmaxf(r0, __shfl_xor_sync(0xffffffffu, r0, 1));
        r0 = fmaxf(r0, __shfl_xor_sync(0xffffffffu, r0, 2));
        r1 = fmaxf(r1, __shfl_xor_sync(0xffffffffu, r1, 1));
        r1 = fmaxf(r1, __shfl_xor_sync(0xffffffffu, r1, 2));
        float mn0 = fmaxf(m0, r0), mn1 = fmaxf(m1, r1);
        float rs0 = fexp(m0 - mn0), rs1 = fexp(m1 - mn1);
        float sum0 = 0.f, sum1 = 0.f;
        unsigned pu[8][4];
#pragma unroll
        for (int nf = 0; nf < 8; nf++) {
            float p00 = fexp(sfr[nf][0] - mn0);
            float p01 = fexp(sfr[nf][1] - mn0);
            float p10 = fexp(sfr[nf][2] - mn1);
            float p11 = fexp(sfr[nf][3] - mn1);
            sum0 += p00 + p01; sum1 += p10 + p11;
            pu[nf][0] = f2tf(p00); pu[nf][1] = f2tf(p01);
            pu[nf][2] = f2tf(p10); pu[nf][3] = f2tf(p11);
        }
        sum0 += __shfl_xor_sync(0xffffffffu, sum0, 1);
        sum0 += __shfl_xor_sync(0xffffffffu, sum0, 2);
        sum1 += __shfl_xor_sync(0xffffffffu, sum1, 1);
        sum1 += __shfl_xor_sync(0xffffffffu, sum1, 2);
        l0 = l0 * rs0 + sum0; m0 = mn0;
        l1 = l1 * rs1 + sum1; m1 = mn1;

        // ---- rescale O (rows lq -> rs0, rows lq+8 -> rs1) ----
#pragma unroll
        for (int nf = 0; nf < 16; nf++) {
            ofr[nf][0] *= rs0; ofr[nf][1] *= rs0;
            ofr[nf][2] *= rs1; ofr[nf][3] *= rs1;
        }

        // ---- O += P V : A = P frags via shfl, B = V natural -----------------
#pragma unroll
        for (int kk = 0; kk < 8; kk++) {
            unsigned x0 = __shfl_sync(0xffffffffu, pu[kk][0], srcA);
            unsigned x1 = __shfl_sync(0xffffffffu, pu[kk][1], srcA);
            unsigned y0 = __shfl_sync(0xffffffffu, pu[kk][2], srcA);
            unsigned y1 = __shfl_sync(0xffffffffu, pu[kk][3], srcA);
            unsigned z0 = __shfl_sync(0xffffffffu, pu[kk][0], srcB);
            unsigned z1 = __shfl_sync(0xffffffffu, pu[kk][1], srcB);
            unsigned w0 = __shfl_sync(0xffffffffu, pu[kk][2], srcB);
            unsigned w1 = __shfl_sync(0xffffffffu, pu[kk][3], srcB);
            unsigned a0 = odd ? x1 : x0;
            unsigned a1 = odd ? y1 : y0;
            unsigned a2 = odd ? z1 : z0;
            unsigned a3 = odd ? w1 : w0;
            const unsigned* v0 = &Vb[(kk * 8 + lr) * KVS + lq];
            const unsigned* v1 = &Vb[(kk * 8 + lr + 4) * KVS + lq];
#pragma unroll
            for (int nf = 0; nf < 16; nf++) {
                mma_tf32(ofr[nf], a0, a1, a2, a3, v0[nf * 8], v1[nf * 8]);
            }
        }
    }

    // ---- epilogue: normalize, tf32-round, icol8-interleave into Y -----------
    float inv0 = 1.0f / l0, inv1 = 1.0f / l1;
    const int c0n = 2 * lr, c1n = 2 * lr + 1;
    const int ic0n = ((c0n & 3) << 1) | (c0n >> 2);
    const int ic1n = ((c1n & 3) << 1) | (c1n >> 2);
    float* ya = Y + (size_t)(qb + qw + lq) * D_MODEL + h * HDIM;
    float* yb = ya + 8 * (size_t)D_MODEL;
#pragma unroll
    for (int nf = 0; nf < 16; nf++) {
        ya[nf * 8 + ic0n] = __uint_as_float(f2tf(ofr[nf][0] * inv0));
        ya[nf * 8 + ic1n] = __uint_as_float(f2tf(ofr[nf][1] * inv0));
        yb[nf * 8 + ic0n] = __uint_as_float(f2tf(ofr[nf][2] * inv1));
        yb[nf * 8 + ic1n] = __uint_as_float(f2tf(ofr[nf][3] * inv1));
    }
}

// ---------------- launch ------------------------------------------------------
extern "C" void kernel_launch(void* const* d_in, const int* in_sizes, int n_in,
                              void* d_out, int out_size) {
    const float* x        = (const float*)d_in[0];
    const float* ve       = (const float*)d_in[1];
    const float* qkv_w    = (const float*)d_in[2];
    const float* lambdas  = (const float*)d_in[3];
    const float* c_proj_w = (const float*)d_in[4];
    float* out = (float*)d_out;

    float *p_qkv, *p_q, *p_k, *p_v, *p_y, *p_xi, *p_wi, *p_cpi;
    cudaGetSymbolAddress((void**)&p_qkv, g_qkv);
    cudaGetSymbolAddress((void**)&p_q, g_q);
    cudaGetSymbolAddress((void**)&p_k, g_k);
    cudaGetSymbolAddress((void**)&p_v, g_v);
    cudaGetSymbolAddress((void**)&p_y, g_y);
    cudaGetSymbolAddress((void**)&p_xi, g_xi);
    cudaGetSymbolAddress((void**)&p_wi, g_wi);
    cudaGetSymbolAddress((void**)&p_cpi, g_cpi);

    static bool attr_set = false;
    if (!attr_set) {
        cudaFuncSetAttribute(gemm3, cudaFuncAttributeMaxDynamicSharedMemorySize,
                             GEMM_SMEM);
        cudaFuncSetAttribute(attn_tf32, cudaFuncAttributeMaxDynamicSharedMemorySize,
                             ATTN_SMEM);
        attr_set = true;
    }

    conv_ilv<<<4096, 256>>>(x, p_xi, T_LEN * D_MODEL / 4);
    conv_ilv<<<3072, 256>>>(qkv_w, p_wi, 3 * D_MODEL * D_MODEL / 4);
    conv_ilv<<<1024, 256>>>(c_proj_w, p_cpi, D_MODEL * D_MODEL / 4);

    gemm3<<<dim3(3 * D_MODEL / 128, T_LEN / 128), 256, GEMM_SMEM>>>(
        p_xi, p_wi, p_qkv, T_LEN, 3 * D_MODEL, D_MODEL);

    qkv_post<<<dim3(T_LEN, NHEAD), 128>>>(p_qkv, ve, lambdas, p_q, p_k, p_v);

    attn_tf32<<<dim3(T_LEN / 128, NHEAD), 256, ATTN_SMEM>>>(p_q, p_k, p_v, p_y);

    gemm3<<<dim3(D_MODEL / 128, T_LEN / 128), 256, GEMM_SMEM>>>(
        p_y, p_cpi, out, T_LEN, D_MODEL, D_MODEL);
}